// round 2
// baseline (speedup 1.0000x reference)
#include <cuda_runtime.h>
#include <stdint.h>

// Problem constants
#define BATCH 32
#define CHAN 3
#define HH 512
#define WW 512
#define G 8            // tile grid
#define TH 64          // tile height
#define TW 64          // tile width
#define BINS 256
#define CLIP_VAL 32    // int(2.0 * 4096 / 256)
#define N_BC (BATCH*CHAN)              // 96
#define N_TILES (N_BC*G*G)             // 6144
#define N_PIX ((size_t)N_BC*HH*WW)     // 25,165,824

// Scratch (static device globals — no allocation)
__device__ uint8_t g_img[N_PIX];
__device__ uint8_t g_lut[(size_t)N_TILES * BINS];

__device__ __forceinline__ int quant(float v) {
    v = fminf(fmaxf(v, 0.0f), 1.0f);
    return (int)rintf(v * 255.0f);    // half-to-even, matches jnp.round
}

// ---------------------------------------------------------------------------
// Kernel 1: per-tile histogram -> clip/redistribute -> CDF -> u8 LUT.
// One block per tile, 256 threads. Also writes the quantized u8 image.
// Each thread covers a contiguous 4-px run: float4 load, uchar4 store.
// ---------------------------------------------------------------------------
__global__ __launch_bounds__(256) void hist_kernel(const float* __restrict__ x) {
    const int tile = blockIdx.x;           // 0..6143
    const int bc   = tile >> 6;            // /64
    const int tloc = tile & 63;
    const int ty   = tloc >> 3;
    const int tx   = tloc & 7;

    __shared__ int hist[BINS];
    __shared__ int red[BINS];
    __shared__ int sc[BINS];

    const int t = threadIdx.x;             // 0..255
    hist[t] = 0;
    __syncthreads();

    // tile pixel base
    const size_t base = (size_t)bc * (HH * WW) + (size_t)ty * TH * WW + (size_t)tx * TW;
    const int col4 = (t & 15) * 4;         // 0,4,...,60
    const int r0   = t >> 4;               // 0..15

    #pragma unroll
    for (int i = 0; i < 4; i++) {
        const int r = r0 + i * 16;
        const size_t off = base + (size_t)r * WW + col4;
        const float4 v = *(const float4*)(x + off);
        const int q0 = quant(v.x);
        const int q1 = quant(v.y);
        const int q2 = quant(v.z);
        const int q3 = quant(v.w);
        *(uchar4*)(g_img + off) = make_uchar4((uint8_t)q0, (uint8_t)q1,
                                              (uint8_t)q2, (uint8_t)q3);
        atomicAdd(&hist[q0], 1);
        atomicAdd(&hist[q1], 1);
        atomicAdd(&hist[q2], 1);
        atomicAdd(&hist[q3], 1);
    }
    __syncthreads();

    // clip + excess reduction
    const int h = hist[t];
    const int c = min(h, CLIP_VAL);
    red[t] = h - c;
    __syncthreads();
    #pragma unroll
    for (int s = 128; s > 0; s >>= 1) {
        if (t < s) red[t] += red[t + s];
        __syncthreads();
    }
    const int excess    = red[0];
    const int batch_add = excess >> 8;
    const int residual  = excess - (batch_add << 8);
    const int step      = max(BINS / max(residual, 1), 1);
    const int add       = ((t % step) == 0 && (t / step) < residual) ? 1 : 0;

    // inclusive scan of hist_final (Hillis-Steele over 256 lanes)
    sc[t] = c + batch_add + add;
    __syncthreads();
    #pragma unroll
    for (int s = 1; s < BINS; s <<= 1) {
        int v2 = (t >= s) ? sc[t - s] : 0;
        __syncthreads();
        sc[t] += v2;
        __syncthreads();
    }

    const float lut_scale = 255.0f / 4096.0f;     // exact in binary
    float lv = rintf((float)sc[t] * lut_scale);
    lv = fminf(fmaxf(lv, 0.0f), 255.0f);
    g_lut[(size_t)tile * BINS + t] = (uint8_t)lv;
}

// ---------------------------------------------------------------------------
// Kernel 2: bilinear LUT interpolation. One thread per 4 horizontal pixels.
// Exactly replicates reference float arithmetic (no fma, left-assoc adds).
// ---------------------------------------------------------------------------
__global__ __launch_bounds__(256) void interp_kernel(float* __restrict__ out) {
    const int idx  = blockIdx.x * blockDim.x + threadIdx.x;
    const int x4   = idx & 127;            // 128 groups of 4 pixels per row
    const int rest = idx >> 7;
    const int y    = rest & 511;
    const int bc   = rest >> 9;
    if (bc >= N_BC) return;

    // vertical interpolation coefficients
    const float fy = (float)y * (1.0f / 64.0f) - 0.5f;
    int ty1 = (int)floorf(fy);
    const float ya = fy - (float)ty1;
    const int ty2 = min(ty1 + 1, G - 1);
    ty1 = max(ty1, 0);
    const float wy1 = 1.0f - ya;
    const float wy2 = ya;

    const size_t pix = ((size_t)bc * HH + y) * WW + (size_t)x4 * 4;
    const uchar4 q4 = *(const uchar4*)(g_img + pix);
    const uint8_t* __restrict__ lutb = g_lut + (size_t)bc * (G * G * BINS);

    const unsigned q[4] = {q4.x, q4.y, q4.z, q4.w};
    float o[4];

    #pragma unroll
    for (int j = 0; j < 4; j++) {
        const int xx = x4 * 4 + j;
        const float fx = (float)xx * (1.0f / 64.0f) - 0.5f;
        int tx1 = (int)floorf(fx);
        const float xa = fx - (float)tx1;
        const int tx2 = min(tx1 + 1, G - 1);
        tx1 = max(tx1, 0);
        const float wx1 = 1.0f - xa;
        const float wx2 = xa;

        const int r1 = ty1 * G;
        const int r2 = ty2 * G;
        const float v11 = (float)lutb[(r1 + tx1) * BINS + q[j]];
        const float v12 = (float)lutb[(r1 + tx2) * BINS + q[j]];
        const float v21 = (float)lutb[(r2 + tx1) * BINS + q[j]];
        const float v22 = (float)lutb[(r2 + tx2) * BINS + q[j]];

        // match reference: res = v11*(wy1*wx1) + v12*(wy1*wx2) + v21*(wy2*wx1) + v22*(wy2*wx2)
        const float w11 = __fmul_rn(wy1, wx1);
        const float w12 = __fmul_rn(wy1, wx2);
        const float w21 = __fmul_rn(wy2, wx1);
        const float w22 = __fmul_rn(wy2, wx2);
        float res = __fmul_rn(v11, w11);
        res = __fadd_rn(res, __fmul_rn(v12, w12));
        res = __fadd_rn(res, __fmul_rn(v21, w21));
        res = __fadd_rn(res, __fmul_rn(v22, w22));

        float r = rintf(res);
        r = fminf(fmaxf(r, 0.0f), 255.0f);
        o[j] = r * (1.0f / 255.0f);
    }

    *(float4*)(out + pix) = make_float4(o[0], o[1], o[2], o[3]);
}

extern "C" void kernel_launch(void* const* d_in, const int* in_sizes, int n_in,
                              void* d_out, int out_size) {
    const float* x = (const float*)d_in[0];
    float* out = (float*)d_out;

    hist_kernel<<<N_TILES, 256>>>(x);

    const int total_threads = N_BC * HH * (WW / 4);   // 6,291,456
    interp_kernel<<<total_threads / 256, 256>>>(out);
}

// round 3
// speedup vs baseline: 1.3239x; 1.3239x over previous
#include <cuda_runtime.h>
#include <stdint.h>

#define BATCH 32
#define CHAN 3
#define HH 512
#define WW 512
#define G 8
#define BINS 256
#define CLIP_VAL 32
#define N_BC (BATCH*CHAN)              // 96
#define N_TILES (N_BC*G*G)             // 6144
#define N_PIX ((size_t)N_BC*HH*WW)     // 25,165,824

__device__ uint8_t g_img[N_PIX];
__device__ uint8_t g_lut[(size_t)N_TILES * BINS];

__device__ __forceinline__ int quant(float v) {
    v = fminf(fmaxf(v, 0.0f), 1.0f);
    return (int)rintf(v * 255.0f);    // half-to-even, matches jnp.round
}

// ---------------------------------------------------------------------------
// Kernel 1: per-tile histogram -> clip/redistribute -> CDF -> u8 LUT.
// One block per 64x64 tile, 256 threads. Also writes quantized u8 image.
// Warp-shuffle scan/reduce: only 4 block barriers.
// ---------------------------------------------------------------------------
__global__ __launch_bounds__(256) void hist_kernel(const float* __restrict__ x) {
    const int tile = blockIdx.x;
    const int bc   = tile >> 6;
    const int tloc = tile & 63;
    const int ty   = tloc >> 3;
    const int tx   = tloc & 7;

    __shared__ int hist[BINS];
    __shared__ int wtmp[8];

    const int t    = threadIdx.x;
    const int lane = t & 31;
    const int w    = t >> 5;
    hist[t] = 0;
    __syncthreads();

    const size_t base = (size_t)bc * (HH * WW) + (size_t)ty * 64 * WW + (size_t)tx * 64;
    const int col4 = (t & 15) * 4;
    const int r0   = t >> 4;

    #pragma unroll
    for (int i = 0; i < 4; i++) {
        const int r = r0 + i * 16;
        const size_t off = base + (size_t)r * WW + col4;
        const float4 v = *(const float4*)(x + off);
        const int q0 = quant(v.x);
        const int q1 = quant(v.y);
        const int q2 = quant(v.z);
        const int q3 = quant(v.w);
        *(uchar4*)(g_img + off) = make_uchar4((uint8_t)q0, (uint8_t)q1,
                                              (uint8_t)q2, (uint8_t)q3);
        atomicAdd(&hist[q0], 1);
        atomicAdd(&hist[q1], 1);
        atomicAdd(&hist[q2], 1);
        atomicAdd(&hist[q3], 1);
    }
    __syncthreads();

    const int h = hist[t];
    const int c = min(h, CLIP_VAL);

    // excess reduction via shuffles
    int e = h - c;
    #pragma unroll
    for (int s = 16; s > 0; s >>= 1) e += __shfl_down_sync(0xffffffffu, e, s);
    if (lane == 0) wtmp[w] = e;
    __syncthreads();
    int excess = 0;
    #pragma unroll
    for (int k = 0; k < 8; k++) excess += wtmp[k];   // broadcast reads

    const int batch_add = excess >> 8;
    const int residual  = excess - (batch_add << 8);
    const int step      = max(BINS / max(residual, 1), 1);
    const int add       = ((t % step) == 0 && (t / step) < residual) ? 1 : 0;

    // inclusive scan of hist_final: warp shuffle scan + warp offsets
    int val = c + batch_add + add;
    #pragma unroll
    for (int s = 1; s < 32; s <<= 1) {
        int u = __shfl_up_sync(0xffffffffu, val, s);
        if (lane >= s) val += u;
    }
    __syncthreads();               // wtmp reuse
    if (lane == 31) wtmp[w] = val;
    __syncthreads();
    int off = 0;
    #pragma unroll
    for (int k = 0; k < 7; k++) if (k < w) off += wtmp[k];
    const int cdf = val + off;

    const float lut_scale = 255.0f / 4096.0f;   // exact
    float lv = rintf((float)cdf * lut_scale);
    lv = fminf(fmaxf(lv, 0.0f), 255.0f);
    g_lut[(size_t)tile * BINS + t] = (uint8_t)lv;
}

// ---------------------------------------------------------------------------
// Kernel 2: bilinear LUT interpolation, quad-packed shared LUT.
// Block = (bc, 32-row band). ty1/ty2 constant per band; only 9 (tx1,tx2)
// pairs exist, so pre-pack quad[p][q] = (v11,v21,v12,v22) as float4 in smem.
// Per pixel: 1 LDS.128 + 5 flops. All arithmetic exact -> bit-identical.
// ---------------------------------------------------------------------------
__global__ __launch_bounds__(256) void interp_kernel(float* __restrict__ out) {
    __shared__ float4 quad[9 * 256];   // 36 KB

    const int blk  = blockIdx.x;
    const int band = blk & 15;         // 32-row band
    const int bc   = blk >> 4;
    const int t    = threadIdx.x;

    // vertical tile pair for this band
    const int ty1r = (band - 1) >> 1;  // arithmetic shift
    const int ty1  = max(ty1r, 0);
    const int ty2  = min(ty1r + 1, 7);

    // build quad table: thread t = bin q, loop over 9 x-pairs (coalesced LDGs)
    {
        const uint8_t* __restrict__ lutb = g_lut + (size_t)bc * (64 * BINS);
        const uint8_t* __restrict__ l1 = lutb + ty1 * 8 * BINS;
        const uint8_t* __restrict__ l2 = lutb + ty2 * 8 * BINS;
        #pragma unroll
        for (int p = 0; p < 9; p++) {
            const int tx1 = max(p - 1, 0);
            const int tx2 = min(p, 7);
            const float v11 = (float)l1[tx1 * BINS + t];
            const float v21 = (float)l2[tx1 * BINS + t];
            const float v12 = (float)l1[tx2 * BINS + t];
            const float v22 = (float)l2[tx2 * BINS + t];
            quad[p * 256 + t] = make_float4(v11, v21, v12, v22);
        }
    }
    __syncthreads();

    // this thread owns x-group x4g (4 px) for all 32 rows; row parity from t
    const int x4g    = t & 127;
    const int rowpar = t >> 7;
    const int x0     = x4g * 4;
    const int p      = (x0 + 32) >> 6;          // constant within 4-px group
    const float4* __restrict__ qrow = quad + p * 256;

    // horizontal weights (exact dyadics), fixed per thread
    float wx1v[4], wx2v[4];
    #pragma unroll
    for (int j = 0; j < 4; j++) {
        const float xa = (float)((x0 + j + 32) & 63) * 0.015625f;
        wx1v[j] = 1.0f - xa;
        wx2v[j] = xa;
    }

    const int ybase = band * 32;
    const size_t bcoff = (size_t)bc * (HH * WW);

    #pragma unroll 4
    for (int i = 0; i < 16; i++) {
        const int y = ybase + 2 * i + rowpar;
        const float ya  = (float)((y + 32) & 63) * 0.015625f;
        const float wy1 = 1.0f - ya;
        const float wy2 = ya;

        const size_t pix = bcoff + (size_t)y * WW + x0;
        const uchar4 q4 = *(const uchar4*)(g_img + pix);
        const unsigned qq[4] = {q4.x, q4.y, q4.z, q4.w};

        float o[4];
        #pragma unroll
        for (int j = 0; j < 4; j++) {
            const float4 v = qrow[qq[j]];
            // exact: wy1*(v11*wx1 + v12*wx2) + wy2*(v21*wx1 + v22*wx2)
            const float t1 = fmaf(v.z, wx2v[j], v.x * wx1v[j]);
            const float t2 = fmaf(v.w, wx2v[j], v.y * wx1v[j]);
            const float res = fmaf(wy2, t2, wy1 * t1);
            float r = rintf(res);
            r = fminf(fmaxf(r, 0.0f), 255.0f);
            o[j] = r * (1.0f / 255.0f);
        }
        *(float4*)(out + pix) = make_float4(o[0], o[1], o[2], o[3]);
    }
}

extern "C" void kernel_launch(void* const* d_in, const int* in_sizes, int n_in,
                              void* d_out, int out_size) {
    const float* x = (const float*)d_in[0];
    float* out = (float*)d_out;

    hist_kernel<<<N_TILES, 256>>>(x);
    interp_kernel<<<N_BC * 16, 256>>>(out);
}

// round 4
// speedup vs baseline: 1.3824x; 1.0441x over previous
#include <cuda_runtime.h>
#include <stdint.h>

#define BATCH 32
#define CHAN 3
#define HH 512
#define WW 512
#define G 8
#define BINS 256
#define CLIP_VAL 32
#define N_BC (BATCH*CHAN)              // 96
#define N_TILES (N_BC*G*G)             // 6144
#define N_PIX ((size_t)N_BC*HH*WW)     // 25,165,824

__device__ uint8_t g_img[N_PIX];
__device__ uint8_t g_lut[(size_t)N_TILES * BINS];

__device__ __forceinline__ int quant(float v) {
    v = fminf(fmaxf(v, 0.0f), 1.0f);
    return (int)rintf(v * 255.0f);    // half-to-even, matches jnp.round
}

// ---------------------------------------------------------------------------
// Kernel 1: per-tile histogram -> clip/redistribute -> CDF -> u8 LUT.
// One block per 64x64 tile, 256 threads. Also writes quantized u8 image.
// ---------------------------------------------------------------------------
__global__ __launch_bounds__(256) void hist_kernel(const float* __restrict__ x) {
    const int tile = blockIdx.x;
    const int bc   = tile >> 6;
    const int tloc = tile & 63;
    const int ty   = tloc >> 3;
    const int tx   = tloc & 7;

    __shared__ int hist[BINS];
    __shared__ int wtmp[8];

    const int t    = threadIdx.x;
    const int lane = t & 31;
    const int w    = t >> 5;
    hist[t] = 0;
    __syncthreads();

    const size_t base = (size_t)bc * (HH * WW) + (size_t)ty * 64 * WW + (size_t)tx * 64;
    const int col4 = (t & 15) * 4;
    const int r0   = t >> 4;

    #pragma unroll
    for (int i = 0; i < 4; i++) {
        const int r = r0 + i * 16;
        const size_t off = base + (size_t)r * WW + col4;
        const float4 v = *(const float4*)(x + off);
        const int q0 = quant(v.x);
        const int q1 = quant(v.y);
        const int q2 = quant(v.z);
        const int q3 = quant(v.w);
        *(uchar4*)(g_img + off) = make_uchar4((uint8_t)q0, (uint8_t)q1,
                                              (uint8_t)q2, (uint8_t)q3);
        atomicAdd(&hist[q0], 1);
        atomicAdd(&hist[q1], 1);
        atomicAdd(&hist[q2], 1);
        atomicAdd(&hist[q3], 1);
    }
    __syncthreads();

    const int h = hist[t];
    const int c = min(h, CLIP_VAL);

    // excess reduction via shuffles
    int e = h - c;
    #pragma unroll
    for (int s = 16; s > 0; s >>= 1) e += __shfl_down_sync(0xffffffffu, e, s);
    if (lane == 0) wtmp[w] = e;
    __syncthreads();
    int excess = 0;
    #pragma unroll
    for (int k = 0; k < 8; k++) excess += wtmp[k];

    const int batch_add = excess >> 8;
    const int residual  = excess - (batch_add << 8);
    const int step      = max(BINS / max(residual, 1), 1);
    const int add       = ((t % step) == 0 && (t / step) < residual) ? 1 : 0;

    // inclusive scan: warp shuffle scan + warp offsets
    int val = c + batch_add + add;
    #pragma unroll
    for (int s = 1; s < 32; s <<= 1) {
        int u = __shfl_up_sync(0xffffffffu, val, s);
        if (lane >= s) val += u;
    }
    __syncthreads();
    if (lane == 31) wtmp[w] = val;
    __syncthreads();
    int off = 0;
    #pragma unroll
    for (int k = 0; k < 7; k++) if (k < w) off += wtmp[k];
    const int cdf = val + off;

    const float lut_scale = 255.0f / 4096.0f;   // exact
    float lv = rintf((float)cdf * lut_scale);
    lv = fminf(fmaxf(lv, 0.0f), 255.0f);
    g_lut[(size_t)tile * BINS + t] = (uint8_t)lv;
}

// ---------------------------------------------------------------------------
// Kernel 2: bilinear LUT interpolation with BYTE-PACKED quad table.
// quad32[p][q] packs (v11,v21,v12,v22) as 4 u8 in one 32-bit word:
// per pixel gather = 1 LDS.32 (9 KB table), extraction via I2F byte-select.
// All arithmetic exact -> bit-identical to reference.
// ---------------------------------------------------------------------------
__global__ __launch_bounds__(256) void interp_kernel(float* __restrict__ out) {
    __shared__ uint32_t quad32[9 * 256];   // 9 KB

    const int blk  = blockIdx.x;
    const int band = blk & 15;         // 32-row band
    const int bc   = blk >> 4;
    const int t    = threadIdx.x;

    const int ty1r = (band - 1) >> 1;
    const int ty1  = max(ty1r, 0);
    const int ty2  = min(ty1r + 1, 7);

    // build packed quad table: thread t = bin q, 9 x-pairs (coalesced u8 LDGs)
    {
        const uint8_t* __restrict__ lutb = g_lut + (size_t)bc * (64 * BINS);
        const uint8_t* __restrict__ l1 = lutb + ty1 * 8 * BINS;
        const uint8_t* __restrict__ l2 = lutb + ty2 * 8 * BINS;
        #pragma unroll
        for (int p = 0; p < 9; p++) {
            const int tx1 = max(p - 1, 0);
            const int tx2 = min(p, 7);
            const uint32_t v11 = l1[tx1 * BINS + t];
            const uint32_t v21 = l2[tx1 * BINS + t];
            const uint32_t v12 = l1[tx2 * BINS + t];
            const uint32_t v22 = l2[tx2 * BINS + t];
            quad32[p * 256 + t] = v11 | (v21 << 8) | (v12 << 16) | (v22 << 24);
        }
    }
    __syncthreads();

    const int x4g    = t & 127;
    const int rowpar = t >> 7;
    const int x0     = x4g * 4;
    const int p      = (x0 + 32) >> 6;
    const uint32_t* __restrict__ qrow = quad32 + p * 256;

    float wx1v[4], wx2v[4];
    #pragma unroll
    for (int j = 0; j < 4; j++) {
        const float xa = (float)((x0 + j + 32) & 63) * 0.015625f;
        wx1v[j] = 1.0f - xa;
        wx2v[j] = xa;
    }

    const int ybase = band * 32;
    const size_t bcoff = (size_t)bc * (HH * WW);

    #pragma unroll 4
    for (int i = 0; i < 16; i++) {
        const int y = ybase + 2 * i + rowpar;
        const float ya  = (float)((y + 32) & 63) * 0.015625f;
        const float wy1 = 1.0f - ya;
        const float wy2 = ya;

        const size_t pix = bcoff + (size_t)y * WW + x0;
        const uchar4 q4 = *(const uchar4*)(g_img + pix);
        const unsigned qq[4] = {q4.x, q4.y, q4.z, q4.w};

        float o[4];
        #pragma unroll
        for (int j = 0; j < 4; j++) {
            const uint32_t wq = qrow[qq[j]];
            const float v11 = (float)(wq & 0xffu);
            const float v21 = (float)((wq >> 8) & 0xffu);
            const float v12 = (float)((wq >> 16) & 0xffu);
            const float v22 = (float)(wq >> 24);
            // exact: wy1*(v11*wx1 + v12*wx2) + wy2*(v21*wx1 + v22*wx2)
            const float t1 = fmaf(v12, wx2v[j], v11 * wx1v[j]);
            const float t2 = fmaf(v22, wx2v[j], v21 * wx1v[j]);
            const float res = fmaf(wy2, t2, wy1 * t1);
            // res is a convex combination of [0,255] values -> no clamp needed
            o[j] = rintf(res) * (1.0f / 255.0f);
        }
        *(float4*)(out + pix) = make_float4(o[0], o[1], o[2], o[3]);
    }
}

extern "C" void kernel_launch(void* const* d_in, const int* in_sizes, int n_in,
                              void* d_out, int out_size) {
    const float* x = (const float*)d_in[0];
    float* out = (float*)d_out;

    hist_kernel<<<N_TILES, 256>>>(x);
    interp_kernel<<<N_BC * 16, 256>>>(out);
}

// round 5
// speedup vs baseline: 1.5537x; 1.1240x over previous
#include <cuda_runtime.h>
#include <stdint.h>

#define BATCH 32
#define CHAN 3
#define HH 512
#define WW 512
#define G 8
#define BINS 256
#define CLIP_VAL 32
#define N_BC (BATCH*CHAN)              // 96
#define N_TILES (N_BC*G*G)             // 6144
#define N_PIX ((size_t)N_BC*HH*WW)     // 25,165,824

__device__ uint8_t g_img[N_PIX];
__device__ uint8_t g_lut[(size_t)N_TILES * BINS];

__device__ __forceinline__ int quant(float v) {
    v = fminf(fmaxf(v, 0.0f), 1.0f);
    return (int)rintf(v * 255.0f);    // half-to-even, matches jnp.round
}

// ---------------------------------------------------------------------------
// Kernel 1: per-tile histogram -> clip/redistribute -> CDF -> u8 LUT.
// One block per 64x64 tile, 256 threads. Also writes quantized u8 image.
// ---------------------------------------------------------------------------
__global__ __launch_bounds__(256) void hist_kernel(const float* __restrict__ x) {
    const int tile = blockIdx.x;
    const int bc   = tile >> 6;
    const int tloc = tile & 63;
    const int ty   = tloc >> 3;
    const int tx   = tloc & 7;

    __shared__ int hist[BINS];
    __shared__ int wtmp[8];

    const int t    = threadIdx.x;
    const int lane = t & 31;
    const int w    = t >> 5;
    hist[t] = 0;

    const size_t base = (size_t)bc * (HH * WW) + (size_t)ty * 64 * WW + (size_t)tx * 64;
    const int col4 = (t & 15) * 4;
    const int r0   = t >> 4;

    // batch all 4 loads up front (MLP=4)
    float4 v[4];
    #pragma unroll
    for (int i = 0; i < 4; i++) {
        const int r = r0 + i * 16;
        v[i] = *(const float4*)(x + base + (size_t)r * WW + col4);
    }
    __syncthreads();

    #pragma unroll
    for (int i = 0; i < 4; i++) {
        const int r = r0 + i * 16;
        const size_t off = base + (size_t)r * WW + col4;
        const int q0 = quant(v[i].x);
        const int q1 = quant(v[i].y);
        const int q2 = quant(v[i].z);
        const int q3 = quant(v[i].w);
        *(uchar4*)(g_img + off) = make_uchar4((uint8_t)q0, (uint8_t)q1,
                                              (uint8_t)q2, (uint8_t)q3);
        atomicAdd(&hist[q0], 1);
        atomicAdd(&hist[q1], 1);
        atomicAdd(&hist[q2], 1);
        atomicAdd(&hist[q3], 1);
    }
    __syncthreads();

    const int h = hist[t];
    const int c = min(h, CLIP_VAL);

    int e = h - c;
    #pragma unroll
    for (int s = 16; s > 0; s >>= 1) e += __shfl_down_sync(0xffffffffu, e, s);
    if (lane == 0) wtmp[w] = e;
    __syncthreads();
    int excess = 0;
    #pragma unroll
    for (int k = 0; k < 8; k++) excess += wtmp[k];

    const int batch_add = excess >> 8;
    const int residual  = excess - (batch_add << 8);
    const int step      = max(BINS / max(residual, 1), 1);
    const int add       = ((t % step) == 0 && (t / step) < residual) ? 1 : 0;

    int val = c + batch_add + add;
    #pragma unroll
    for (int s = 1; s < 32; s <<= 1) {
        int u = __shfl_up_sync(0xffffffffu, val, s);
        if (lane >= s) val += u;
    }
    __syncthreads();
    if (lane == 31) wtmp[w] = val;
    __syncthreads();
    int off = 0;
    #pragma unroll
    for (int k = 0; k < 7; k++) if (k < w) off += wtmp[k];
    const int cdf = val + off;

    const float lut_scale = 255.0f / 4096.0f;   // exact
    float lv = rintf((float)cdf * lut_scale);
    lv = fminf(fmaxf(lv, 0.0f), 255.0f);
    g_lut[(size_t)tile * BINS + t] = (uint8_t)lv;
}

// ---------------------------------------------------------------------------
// Kernel 2: bilinear LUT interpolation, 16 px/thread per global load.
// quad32[p][q] packs (v11,v21,v12,v22). Per 16-px group p is constant and
// kx affine in j. hv1/hv2 via unsigned dp4a; num < 2^20 so the float
// rounding (num * 2^-12 exact, rintf half-even) is bit-identical to ref.
// ---------------------------------------------------------------------------
__global__ __launch_bounds__(256) void interp_kernel(float* __restrict__ out) {
    __shared__ uint32_t quad32[9 * 256];   // 9 KB

    const int blk  = blockIdx.x;
    const int band = blk & 15;         // 32-row band
    const int bc   = blk >> 4;
    const int t    = threadIdx.x;

    const int ty1r = (band - 1) >> 1;
    const int ty1  = max(ty1r, 0);
    const int ty2  = min(ty1r + 1, 7);

    // build packed quad table: 16 coalesced u8 LDGs per thread, combine in regs
    {
        const uint8_t* __restrict__ lutb = g_lut + (size_t)bc * (64 * BINS);
        const uint8_t* __restrict__ l1 = lutb + ty1 * 8 * BINS;
        const uint8_t* __restrict__ l2 = lutb + ty2 * 8 * BINS;
        uint32_t a1[8], a2[8];
        #pragma unroll
        for (int tx = 0; tx < 8; tx++) {
            a1[tx] = l1[tx * BINS + t];
            a2[tx] = l2[tx * BINS + t];
        }
        #pragma unroll
        for (int p = 0; p < 9; p++) {
            const int tx1 = max(p - 1, 0);
            const int tx2 = min(p, 7);
            quad32[p * 256 + t] = a1[tx1] | (a2[tx1] << 8) |
                                  (a1[tx2] << 16) | (a2[tx2] << 24);
        }
    }
    __syncthreads();

    const int grp = t & 31;            // 16-px group within row
    const int r   = t >> 5;            // row 0..7 within each 8-row pass
    const int x0  = grp * 16;
    const int kbase = (x0 + 32) & 63;  // in {0,16,32,48}; kx=kbase+j, no wrap
    const int p     = (x0 + 32) >> 6;  // constant for all 16 px
    const uint32_t* __restrict__ qrow = quad32 + (p << 8);

    // weight word wA_j = (64-kx) | (kx<<16) is affine in j
    const uint32_t wA0 = (uint32_t)(64 - kbase) | ((uint32_t)kbase << 16);

    const int ybase = band * 32;
    const size_t bcoff = (size_t)bc * (HH * WW);

    // prefetch all 4 passes' pixels (MLP=4)
    uint4 qw[4];
    #pragma unroll
    for (int i = 0; i < 4; i++) {
        const int y = ybase + i * 8 + r;
        qw[i] = *(const uint4*)(g_img + bcoff + (size_t)y * WW + x0);
    }

    #pragma unroll
    for (int i = 0; i < 4; i++) {
        const int y   = ybase + i * 8 + r;
        const int ky  = (y + 32) & 63;
        const int wy1 = 64 - ky;
        const size_t pix = bcoff + (size_t)y * WW + x0;

        const uint32_t words[4] = {qw[i].x, qw[i].y, qw[i].z, qw[i].w};
        #pragma unroll
        for (int wdi = 0; wdi < 4; wdi++) {
            float o[4];
            #pragma unroll
            for (int b = 0; b < 4; b++) {
                const int j = wdi * 4 + b;
                const uint32_t q = (words[wdi] >> (8 * b)) & 0xffu;
                const uint32_t wq = qrow[q];
                const uint32_t wA = wA0 + (uint32_t)j * 0xFFFFu;  // (64-kx)|(kx<<16)
                const uint32_t wB = wA << 8;
                const unsigned hv1 = __dp4a(wq, wA, 0u);  // v11*(64-kx)+v12*kx
                const unsigned hv2 = __dp4a(wq, wB, 0u);  // v21*(64-kx)+v22*kx
                const int num = (int)hv1 * wy1 + (int)hv2 * ky;   // < 2^20
                const float res = (float)num * (1.0f / 4096.0f);  // exact
                o[b] = rintf(res) * (1.0f / 255.0f);
            }
            *(float4*)(out + pix + wdi * 4) = make_float4(o[0], o[1], o[2], o[3]);
        }
    }
}

extern "C" void kernel_launch(void* const* d_in, const int* in_sizes, int n_in,
                              void* d_out, int out_size) {
    const float* x = (const float*)d_in[0];
    float* out = (float*)d_out;

    hist_kernel<<<N_TILES, 256>>>(x);
    interp_kernel<<<N_BC * 16, 256>>>(out);
}